// round 5
// baseline (speedup 1.0000x reference)
#include <cuda_runtime.h>
#include <math.h>
#include <stdint.h>

#define BROWS 8192
#define GAMES 8
#define DIN   512
#define H1D   1024
#define H2D   1024
#define ADIM  128
#define SPLITK 4

// Scratch (device globals — no allocation allowed)
__device__ int   g_perm[BROWS];
__device__ int   g_off[GAMES + 1];
__device__ float g_h1[(size_t)BROWS * H1D];                 // sorted-order hidden1
__device__ float g_hf[(size_t)BROWS * H2D];                 // sorted-order hidden2
__device__ float g_part[(size_t)SPLITK * BROWS * ADIM];    // L3 split-K partials

// ---------------------------------------------------------------------------
// Stable counting sort of rows by game id (G=8). One block, 1024 threads.
// ---------------------------------------------------------------------------
__global__ void perm_kernel(const int* __restrict__ idx) {
    const int NT = 1024;
    const int RPT = BROWS / NT;   // 8 rows per thread
    __shared__ int cnt[NT][GAMES];
    __shared__ int tot[GAMES];
    __shared__ int base[GAMES + 1];

    int t = threadIdx.x;
    int c[GAMES];
#pragma unroll
    for (int g = 0; g < GAMES; g++) c[g] = 0;
    int lg[RPT];
    int r0 = t * RPT;
#pragma unroll
    for (int j = 0; j < RPT; j++) {
        int g = idx[r0 + j];
        lg[j] = g;
        c[g]++;
    }
#pragma unroll
    for (int g = 0; g < GAMES; g++) cnt[t][g] = c[g];
    __syncthreads();

    if (t < GAMES) {
        int s = 0;
        for (int i = 0; i < NT; i++) {
            int v = cnt[i][t];
            cnt[i][t] = s;
            s += v;
        }
        tot[t] = s;
    }
    __syncthreads();
    if (t == 0) {
        int s = 0;
        for (int g = 0; g < GAMES; g++) {
            base[g] = s;
            g_off[g] = s;
            s += tot[g];
        }
        base[GAMES] = s;
        g_off[GAMES] = s;
    }
    __syncthreads();

    int pos[GAMES];
#pragma unroll
    for (int g = 0; g < GAMES; g++) pos[g] = base[g] + cnt[t][g];
#pragma unroll
    for (int j = 0; j < RPT; j++) {
        int g = lg[j];
        g_perm[pos[g]] = r0 + j;
        pos[g]++;
    }
}

// ---------------------------------------------------------------------------
// TF32 helpers
// ---------------------------------------------------------------------------
__device__ __forceinline__ float ftf32(float x) {
    uint32_t u = __float_as_uint(x);
    asm("cvt.rna.tf32.f32 %0, %0;" : "+r"(u));
    return __uint_as_float(u);
}
__device__ __forceinline__ uint32_t fu(float x) { return __float_as_uint(x); }

__device__ __forceinline__ void mma_tf32(float c[4], const uint32_t a[4],
                                         const uint32_t b[2]) {
    asm volatile(
        "mma.sync.aligned.m16n8k8.row.col.f32.tf32.tf32.f32 "
        "{%0,%1,%2,%3}, {%4,%5,%6,%7}, {%8,%9}, {%0,%1,%2,%3};\n"
        : "+f"(c[0]), "+f"(c[1]), "+f"(c[2]), "+f"(c[3])
        : "r"(a[0]), "r"(a[1]), "r"(a[2]), "r"(a[3]), "r"(b[0]), "r"(b[1]));
}

// ---------------------------------------------------------------------------
// Grouped TF32 tensor-core GEMM with fused bias + activation.
// MODE 0: h1[q,:]  = relu(state[perm[q],:] @ W1[g] + b1[g]);  groups from g_off
// MODE 1: hf[q,:]  = relu(h1[q,:] @ W2 + b2);                 dense
// MODE 3: part[kc][q,:] = hf[perm[q],:] @ W3[g] (K-chunk kc); groups from g_off
//         (bias/tanh/scatter applied by l3_reduce)
// ---------------------------------------------------------------------------
template <int BM, int BN, int BK, int WM, int WN, int MODE>
__global__ void __launch_bounds__((BM / WM) * (BN / WN) * 32, 3)
mma_gemm(const float* __restrict__ Ain,
         const float* __restrict__ Wfull,
         const float* __restrict__ biasfull,
         float* __restrict__ Out,
         int K, int N) {
    constexpr int THREADS = (BM / WM) * (BN / WN) * 32;
    constexpr int LDA = BK + 4;        // 20 words: conflict-free A frag LDS
    constexpr int LDB = BN + 8;        // 136 words: conflict-free B frag LDS
    constexpr int MF = WM / 16;
    constexpr int NF = WN / 8;
    constexpr int AV = BM * BK / 4 / THREADS;   // float4 A-loads / thread
    constexpr int BV = BK * BN / 4 / THREADS;   // float4 B-loads / thread
    static_assert(AV * THREADS * 4 == BM * BK, "A split");
    static_assert(BV * THREADS * 4 == BK * BN, "B split");

    __shared__ float As[2][BM][LDA];
    __shared__ float Bs[2][BK][LDB];
    __shared__ int   rows[BM];

    int rowBeg, rowEnd;
    int g = 0;
    if (MODE == 1) {
        rowBeg = 0;
        rowEnd = BROWS;
    } else {
        g = blockIdx.z;
        rowBeg = g_off[g];
        rowEnd = g_off[g + 1];
    }
    int row0 = rowBeg + blockIdx.y * BM;
    if (row0 >= rowEnd) return;      // over-launched empty group tile
    int kc = 0, kbeg = 0, nk = K / BK;
    int n0 = blockIdx.x * BN;
    if (MODE == 3) {                 // blockIdx.x = K-chunk, single N tile
        kc = blockIdx.x;
        kbeg = kc * (K / SPLITK);
        nk = (K / SPLITK) / BK;
        n0 = 0;
    }
    int tid = threadIdx.x;
    int lane = tid & 31;
    int warp = tid >> 5;
    int wr0 = (warp / (BN / WN)) * WM;
    int wc0 = (warp % (BN / WN)) * WN;
    int qk = lane & 3;
    int qr = lane >> 2;

    if (MODE != 1) {
        for (int i = tid; i < BM; i += THREADS) {
            int q = row0 + i;
            rows[i] = (q < rowEnd) ? g_perm[q] : -1;
        }
        __syncthreads();
    }

    const float* W = Wfull + (MODE == 1 ? (size_t)0 : (size_t)g * K * N);
    const float* Abase = (MODE == 0) ? Ain : (MODE == 1 ? g_h1 : g_hf);

    float4 ra[AV], rb[BV];

    auto fetch = [&](int k0) {
#pragma unroll
        for (int l = 0; l < AV; l++) {
            int v = tid + l * THREADS;
            int m = v / (BK / 4);
            int c4 = (v % (BK / 4)) * 4;
            if (MODE == 1) {
                ra[l] = *(const float4*)(Abase + (size_t)(row0 + m) * K + k0 + c4);
            } else {
                int r = rows[m];
                ra[l] = (r >= 0)
                            ? *(const float4*)(Abase + (size_t)r * K + k0 + c4)
                            : make_float4(0.f, 0.f, 0.f, 0.f);
            }
        }
#pragma unroll
        for (int l = 0; l < BV; l++) {
            int v = tid + l * THREADS;
            int kr = v / (BN / 4);
            int c4 = v % (BN / 4);
            rb[l] = *(const float4*)(W + (size_t)(k0 + kr) * N + n0 + c4 * 4);
        }
    };

    auto stsTiles = [&](int buf) {
#pragma unroll
        for (int l = 0; l < AV; l++) {
            int v = tid + l * THREADS;
            int m = v / (BK / 4);
            int c4 = (v % (BK / 4)) * 4;
            float4 t = ra[l];
            t.x = ftf32(t.x); t.y = ftf32(t.y);
            t.z = ftf32(t.z); t.w = ftf32(t.w);
            *(float4*)&As[buf][m][c4] = t;
        }
#pragma unroll
        for (int l = 0; l < BV; l++) {
            int v = tid + l * THREADS;
            int kr = v / (BN / 4);
            int c4 = v % (BN / 4);
            float4 t = rb[l];
            t.x = ftf32(t.x); t.y = ftf32(t.y);
            t.z = ftf32(t.z); t.w = ftf32(t.w);
            *(float4*)&Bs[buf][kr][c4 * 4] = t;
        }
    };

    float acc[MF][NF][4];
#pragma unroll
    for (int i = 0; i < MF; i++)
#pragma unroll
        for (int j = 0; j < NF; j++)
#pragma unroll
            for (int r = 0; r < 4; r++) acc[i][j][r] = 0.f;

    fetch(kbeg);
    stsTiles(0);
    __syncthreads();

    int buf = 0;
    for (int kt = 0; kt < nk; kt++) {
        if (kt + 1 < nk) fetch(kbeg + (kt + 1) * BK);   // LDG overlaps MMA
#pragma unroll
        for (int ks = 0; ks < BK / 8; ks++) {
            int k0 = ks * 8;
            uint32_t af[MF][4];
            uint32_t bf[NF][2];
#pragma unroll
            for (int i = 0; i < MF; i++) {
                int m = wr0 + i * 16 + qr;
                af[i][0] = fu(As[buf][m][k0 + qk]);
                af[i][1] = fu(As[buf][m + 8][k0 + qk]);
                af[i][2] = fu(As[buf][m][k0 + qk + 4]);
                af[i][3] = fu(As[buf][m + 8][k0 + qk + 4]);
            }
#pragma unroll
            for (int j = 0; j < NF; j++) {
                int n = wc0 + j * 8 + qr;
                bf[j][0] = fu(Bs[buf][k0 + qk][n]);
                bf[j][1] = fu(Bs[buf][k0 + qk + 4][n]);
            }
#pragma unroll
            for (int i = 0; i < MF; i++)
#pragma unroll
                for (int j = 0; j < NF; j++) mma_tf32(acc[i][j], af[i], bf[j]);
        }
        if (kt + 1 < nk) stsTiles(buf ^ 1);
        __syncthreads();
        buf ^= 1;
    }

    // Epilogue. c frag: rows (qr, qr+8), cols 2*qk + {0,1}
    const float* bp = biasfull + (MODE == 1 ? (size_t)0 : (size_t)g * N) + n0;
#pragma unroll
    for (int i = 0; i < MF; i++) {
#pragma unroll
        for (int h = 0; h < 2; h++) {        // row half: qr / qr+8
            int mrow = wr0 + i * 16 + qr + h * 8;
            int q = row0 + mrow;
            if (MODE != 1 && q >= rowEnd) continue;
            float* cr;
            if (MODE == 0)
                cr = g_h1 + (size_t)q * N + n0;
            else if (MODE == 1)
                cr = g_hf + (size_t)q * N + n0;
            else   // MODE 3: raw partial, sorted-position row, coalesced
                cr = g_part + ((size_t)kc * BROWS + q) * ADIM + n0;
#pragma unroll
            for (int j = 0; j < NF; j++) {
                int col = wc0 + j * 8 + 2 * qk;
                float v0 = acc[i][j][h * 2 + 0];
                float v1 = acc[i][j][h * 2 + 1];
                float2 o;
                if (MODE == 3) {
                    o.x = v0;
                    o.y = v1;
                } else {
                    o.x = fmaxf(v0 + bp[col + 0], 0.f);
                    o.y = fmaxf(v1 + bp[col + 1], 0.f);
                }
                *(float2*)(cr + col) = o;
            }
        }
    }
}

// ---------------------------------------------------------------------------
// L3 reduce: sum SPLITK partials, +b3[g], tanh, scatter to out[perm[q]].
// One thread -> 4 cols; 32 threads -> one row. grid*block = 8192*32.
// ---------------------------------------------------------------------------
__global__ void __launch_bounds__(256)
l3_reduce(const float* __restrict__ b3, float* __restrict__ out) {
    __shared__ int soff[GAMES + 1];
    if (threadIdx.x <= GAMES) soff[threadIdx.x] = g_off[threadIdx.x];
    __syncthreads();

    int t = blockIdx.x * blockDim.x + threadIdx.x;
    int q = t >> 5;            // sorted-position row
    int c = (t & 31) * 4;      // column

    int g = 0;
#pragma unroll
    for (int i = 1; i < GAMES; i++) g += (q >= soff[i]);

    float4 s = *(const float4*)(g_part + (size_t)q * ADIM + c);
#pragma unroll
    for (int kc = 1; kc < SPLITK; kc++) {
        float4 p = *(const float4*)(g_part + ((size_t)kc * BROWS + q) * ADIM + c);
        s.x += p.x; s.y += p.y; s.z += p.z; s.w += p.w;
    }
    float4 bb = *(const float4*)(b3 + (size_t)g * ADIM + c);
    float4 o;
    o.x = tanhf(s.x + bb.x);
    o.y = tanhf(s.y + bb.y);
    o.z = tanhf(s.z + bb.z);
    o.w = tanhf(s.w + bb.w);
    int b = g_perm[q];
    *(float4*)(out + (size_t)b * ADIM + c) = o;
}

// ---------------------------------------------------------------------------
extern "C" void kernel_launch(void* const* d_in, const int* in_sizes, int n_in,
                              void* d_out, int out_size) {
    const float* state = (const float*)d_in[0];
    const int*   idx   = (const int*)d_in[1];
    const float* W1    = (const float*)d_in[2];
    const float* b1    = (const float*)d_in[3];
    const float* W2    = (const float*)d_in[4];
    const float* b2    = (const float*)d_in[5];
    const float* W3    = (const float*)d_in[6];
    const float* b3    = (const float*)d_in[7];
    float* out = (float*)d_out;
    (void)in_sizes; (void)n_in; (void)out_size;

    // 1) stable grouping permutation
    perm_kernel<<<1, 1024>>>(idx);

    // 2) L1: per-game 512->1024, gather rows via perm, relu.
    //    16 y-tiles/game covers groups up to 2048 rows (idx~uniform: mean
    //    1024, sd~30 -> >17 sigma margin); empty tiles exit immediately.
    mma_gemm<128, 128, 16, 64, 32, 0>
        <<<dim3(H1D / 128, 16, GAMES), 256>>>(state, W1, b1, nullptr,
                                              DIN, H1D);

    // 3) L2: dense 1024->1024, relu
    mma_gemm<128, 128, 16, 64, 32, 1>
        <<<dim3(H2D / 128, BROWS / 128, 1), 256>>>(nullptr, W2, b2, nullptr,
                                                   H1D, H2D);

    // 4) L3 split-K: per-game 1024->128 partials over K chunks of 256.
    //    x = K-chunk (4), y = 32 row-tiles/game (2048-row capacity), z = game.
    //    ~512 active CTAs vs 128 before.
    mma_gemm<64, 128, 16, 32, 32, 3>
        <<<dim3(SPLITK, 32, GAMES), 256>>>(nullptr, W3, nullptr, nullptr,
                                           H2D, ADIM);

    // 5) reduce + bias + tanh + scatter
    l3_reduce<<<BROWS * 32 / 256, 256>>>(b3, out);
}

// round 6
// speedup vs baseline: 3.2696x; 3.2696x over previous
#include <cuda_runtime.h>
#include <math.h>
#include <stdint.h>

#define BROWS 8192
#define GAMES 8
#define DIN   512
#define H1D   1024
#define H2D   1024
#define ADIM  128
#define SPLITK 8

// Scratch (device globals — no allocation allowed)
__device__ int   g_perm[BROWS];
__device__ int   g_off[GAMES + 1];
__device__ float g_h1[(size_t)BROWS * H1D];                 // sorted-order hidden1
__device__ float g_hf[(size_t)BROWS * H2D];                 // sorted-order hidden2
__device__ float g_part[(size_t)SPLITK * BROWS * ADIM];    // L3 split-K partials

// ---------------------------------------------------------------------------
// Stable counting sort of rows by game id (G=8). One block, 1024 threads.
// ---------------------------------------------------------------------------
__global__ void perm_kernel(const int* __restrict__ idx) {
    const int NT = 1024;
    const int RPT = BROWS / NT;   // 8 rows per thread
    __shared__ int cnt[NT][GAMES];
    __shared__ int tot[GAMES];
    __shared__ int base[GAMES + 1];

    int t = threadIdx.x;
    int c[GAMES];
#pragma unroll
    for (int g = 0; g < GAMES; g++) c[g] = 0;
    int lg[RPT];
    int r0 = t * RPT;
#pragma unroll
    for (int j = 0; j < RPT; j++) {
        int g = idx[r0 + j];
        lg[j] = g;
        c[g]++;
    }
#pragma unroll
    for (int g = 0; g < GAMES; g++) cnt[t][g] = c[g];
    __syncthreads();

    if (t < GAMES) {
        int s = 0;
        for (int i = 0; i < NT; i++) {
            int v = cnt[i][t];
            cnt[i][t] = s;
            s += v;
        }
        tot[t] = s;
    }
    __syncthreads();
    if (t == 0) {
        int s = 0;
        for (int g = 0; g < GAMES; g++) {
            base[g] = s;
            g_off[g] = s;
            s += tot[g];
        }
        base[GAMES] = s;
        g_off[GAMES] = s;
    }
    __syncthreads();

    int pos[GAMES];
#pragma unroll
    for (int g = 0; g < GAMES; g++) pos[g] = base[g] + cnt[t][g];
#pragma unroll
    for (int j = 0; j < RPT; j++) {
        int g = lg[j];
        g_perm[pos[g]] = r0 + j;
        pos[g]++;
    }
}

// ---------------------------------------------------------------------------
// TF32 helpers
// ---------------------------------------------------------------------------
__device__ __forceinline__ float ftf32(float x) {
    uint32_t u = __float_as_uint(x);
    asm("cvt.rna.tf32.f32 %0, %0;" : "+r"(u));
    return __uint_as_float(u);
}
__device__ __forceinline__ uint32_t fu(float x) { return __float_as_uint(x); }

__device__ __forceinline__ void mma_tf32(float c[4], const uint32_t a[4],
                                         const uint32_t b[2]) {
    asm volatile(
        "mma.sync.aligned.m16n8k8.row.col.f32.tf32.tf32.f32 "
        "{%0,%1,%2,%3}, {%4,%5,%6,%7}, {%8,%9}, {%0,%1,%2,%3};\n"
        : "+f"(c[0]), "+f"(c[1]), "+f"(c[2]), "+f"(c[3])
        : "r"(a[0]), "r"(a[1]), "r"(a[2]), "r"(a[3]), "r"(b[0]), "r"(b[1]));
}

// ---------------------------------------------------------------------------
// Grouped TF32 tensor-core GEMM with fused bias + activation.
// MODE 0: h1[q,:]  = relu(state[perm[q],:] @ W1[g] + b1[g]);  groups from g_off
// MODE 1: hf[q,:]  = relu(h1[q,:] @ W2 + b2);                 dense
// MODE 3: part[kc][q,:] = hf[perm[q],:] @ W3[g] (K-chunk kc); groups from g_off
//         (bias/tanh/scatter applied by l3_reduce)
// NOTE: no min-blocks occupancy hint — a forced reg cap makes ptxas spill the
// mainloop (measured 3x regression in R5).
// ---------------------------------------------------------------------------
template <int BM, int BN, int BK, int WM, int WN, int MODE>
__global__ void __launch_bounds__((BM / WM) * (BN / WN) * 32)
mma_gemm(const float* __restrict__ Ain,
         const float* __restrict__ Wfull,
         const float* __restrict__ biasfull,
         float* __restrict__ Out,
         int K, int N) {
    constexpr int THREADS = (BM / WM) * (BN / WN) * 32;
    constexpr int LDA = BK + 4;        // 20 words: conflict-free A frag LDS
    constexpr int LDB = BN + 8;        // 136 words: conflict-free B frag LDS
    constexpr int MF = WM / 16;
    constexpr int NF = WN / 8;
    constexpr int AV = BM * BK / 4 / THREADS;   // float4 A-loads / thread
    constexpr int BV = BK * BN / 4 / THREADS;   // float4 B-loads / thread
    static_assert(AV * THREADS * 4 == BM * BK, "A split");
    static_assert(BV * THREADS * 4 == BK * BN, "B split");

    __shared__ float As[2][BM][LDA];
    __shared__ float Bs[2][BK][LDB];
    __shared__ int   rows[BM];

    int rowBeg, rowEnd;
    int g = 0;
    if (MODE == 1) {
        rowBeg = 0;
        rowEnd = BROWS;
    } else {
        g = blockIdx.z;
        rowBeg = g_off[g];
        rowEnd = g_off[g + 1];
    }
    int row0 = rowBeg + blockIdx.y * BM;
    if (row0 >= rowEnd) return;      // over-launched empty group tile
    int kc = 0, kbeg = 0, nk = K / BK;
    int n0 = blockIdx.x * BN;
    if (MODE == 3) {                 // blockIdx.x = K-chunk, single N tile
        kc = blockIdx.x;
        kbeg = kc * (K / SPLITK);
        nk = (K / SPLITK) / BK;
        n0 = 0;
    }
    int tid = threadIdx.x;
    int lane = tid & 31;
    int warp = tid >> 5;
    int wr0 = (warp / (BN / WN)) * WM;
    int wc0 = (warp % (BN / WN)) * WN;
    int qk = lane & 3;
    int qr = lane >> 2;

    if (MODE != 1) {
        for (int i = tid; i < BM; i += THREADS) {
            int q = row0 + i;
            rows[i] = (q < rowEnd) ? g_perm[q] : -1;
        }
        __syncthreads();
    }

    const float* W = Wfull + (MODE == 1 ? (size_t)0 : (size_t)g * K * N);
    const float* Abase = (MODE == 0) ? Ain : (MODE == 1 ? g_h1 : g_hf);

    float4 ra[AV], rb[BV];

    auto fetch = [&](int k0) {
#pragma unroll
        for (int l = 0; l < AV; l++) {
            int v = tid + l * THREADS;
            int m = v / (BK / 4);
            int c4 = (v % (BK / 4)) * 4;
            if (MODE == 1) {
                ra[l] = *(const float4*)(Abase + (size_t)(row0 + m) * K + k0 + c4);
            } else {
                int r = rows[m];
                ra[l] = (r >= 0)
                            ? *(const float4*)(Abase + (size_t)r * K + k0 + c4)
                            : make_float4(0.f, 0.f, 0.f, 0.f);
            }
        }
#pragma unroll
        for (int l = 0; l < BV; l++) {
            int v = tid + l * THREADS;
            int kr = v / (BN / 4);
            int c4 = v % (BN / 4);
            rb[l] = *(const float4*)(W + (size_t)(k0 + kr) * N + n0 + c4 * 4);
        }
    };

    auto stsTiles = [&](int buf) {
#pragma unroll
        for (int l = 0; l < AV; l++) {
            int v = tid + l * THREADS;
            int m = v / (BK / 4);
            int c4 = (v % (BK / 4)) * 4;
            float4 t = ra[l];
            t.x = ftf32(t.x); t.y = ftf32(t.y);
            t.z = ftf32(t.z); t.w = ftf32(t.w);
            *(float4*)&As[buf][m][c4] = t;
        }
#pragma unroll
        for (int l = 0; l < BV; l++) {
            int v = tid + l * THREADS;
            int kr = v / (BN / 4);
            int c4 = v % (BN / 4);
            float4 t = rb[l];
            t.x = ftf32(t.x); t.y = ftf32(t.y);
            t.z = ftf32(t.z); t.w = ftf32(t.w);
            *(float4*)&Bs[buf][kr][c4 * 4] = t;
        }
    };

    float acc[MF][NF][4];
#pragma unroll
    for (int i = 0; i < MF; i++)
#pragma unroll
        for (int j = 0; j < NF; j++)
#pragma unroll
            for (int r = 0; r < 4; r++) acc[i][j][r] = 0.f;

    fetch(kbeg);
    stsTiles(0);
    __syncthreads();

    int buf = 0;
    for (int kt = 0; kt < nk; kt++) {
        if (kt + 1 < nk) fetch(kbeg + (kt + 1) * BK);   // LDG overlaps MMA
#pragma unroll
        for (int ks = 0; ks < BK / 8; ks++) {
            int k0 = ks * 8;
            uint32_t af[MF][4];
            uint32_t bf[NF][2];
#pragma unroll
            for (int i = 0; i < MF; i++) {
                int m = wr0 + i * 16 + qr;
                af[i][0] = fu(As[buf][m][k0 + qk]);
                af[i][1] = fu(As[buf][m + 8][k0 + qk]);
                af[i][2] = fu(As[buf][m][k0 + qk + 4]);
                af[i][3] = fu(As[buf][m + 8][k0 + qk + 4]);
            }
#pragma unroll
            for (int j = 0; j < NF; j++) {
                int n = wc0 + j * 8 + qr;
                bf[j][0] = fu(Bs[buf][k0 + qk][n]);
                bf[j][1] = fu(Bs[buf][k0 + qk + 4][n]);
            }
#pragma unroll
            for (int i = 0; i < MF; i++)
#pragma unroll
                for (int j = 0; j < NF; j++) mma_tf32(acc[i][j], af[i], bf[j]);
        }
        if (kt + 1 < nk) stsTiles(buf ^ 1);
        __syncthreads();
        buf ^= 1;
    }

    // Epilogue. c frag: rows (qr, qr+8), cols 2*qk + {0,1}
    const float* bp = biasfull + (MODE == 1 ? (size_t)0 : (size_t)g * N) + n0;
#pragma unroll
    for (int i = 0; i < MF; i++) {
#pragma unroll
        for (int h = 0; h < 2; h++) {        // row half: qr / qr+8
            int mrow = wr0 + i * 16 + qr + h * 8;
            int q = row0 + mrow;
            if (MODE != 1 && q >= rowEnd) continue;
            float* cr;
            if (MODE == 0)
                cr = g_h1 + (size_t)q * N + n0;
            else if (MODE == 1)
                cr = g_hf + (size_t)q * N + n0;
            else   // MODE 3: raw partial, sorted-position row, coalesced
                cr = g_part + ((size_t)kc * BROWS + q) * ADIM + n0;
#pragma unroll
            for (int j = 0; j < NF; j++) {
                int col = wc0 + j * 8 + 2 * qk;
                float v0 = acc[i][j][h * 2 + 0];
                float v1 = acc[i][j][h * 2 + 1];
                float2 o;
                if (MODE == 3) {
                    o.x = v0;
                    o.y = v1;
                } else {
                    o.x = fmaxf(v0 + bp[col + 0], 0.f);
                    o.y = fmaxf(v1 + bp[col + 1], 0.f);
                }
                *(float2*)(cr + col) = o;
            }
        }
    }
}

// ---------------------------------------------------------------------------
// L3 reduce: sum SPLITK partials, +b3[g], tanh, scatter to out[perm[q]].
// One thread -> 4 cols; 32 threads -> one row. grid*block = 8192*32.
// ---------------------------------------------------------------------------
__global__ void __launch_bounds__(256)
l3_reduce(const float* __restrict__ b3, float* __restrict__ out) {
    __shared__ int soff[GAMES + 1];
    if (threadIdx.x <= GAMES) soff[threadIdx.x] = g_off[threadIdx.x];
    __syncthreads();

    int t = blockIdx.x * blockDim.x + threadIdx.x;
    int q = t >> 5;            // sorted-position row
    int c = (t & 31) * 4;      // column

    int g = 0;
#pragma unroll
    for (int i = 1; i < GAMES; i++) g += (q >= soff[i]);

    float4 s = *(const float4*)(g_part + (size_t)q * ADIM + c);
#pragma unroll
    for (int kc = 1; kc < SPLITK; kc++) {
        float4 p = *(const float4*)(g_part + ((size_t)kc * BROWS + q) * ADIM + c);
        s.x += p.x; s.y += p.y; s.z += p.z; s.w += p.w;
    }
    float4 bb = *(const float4*)(b3 + (size_t)g * ADIM + c);
    float4 o;
    o.x = tanhf(s.x + bb.x);
    o.y = tanhf(s.y + bb.y);
    o.z = tanhf(s.z + bb.z);
    o.w = tanhf(s.w + bb.w);
    int b = g_perm[q];
    *(float4*)(out + (size_t)b * ADIM + c) = o;
}

// ---------------------------------------------------------------------------
extern "C" void kernel_launch(void* const* d_in, const int* in_sizes, int n_in,
                              void* d_out, int out_size) {
    const float* state = (const float*)d_in[0];
    const int*   idx   = (const int*)d_in[1];
    const float* W1    = (const float*)d_in[2];
    const float* b1    = (const float*)d_in[3];
    const float* W2    = (const float*)d_in[4];
    const float* b2    = (const float*)d_in[5];
    const float* W3    = (const float*)d_in[6];
    const float* b3    = (const float*)d_in[7];
    float* out = (float*)d_out;
    (void)in_sizes; (void)n_in; (void)out_size;

    // 1) stable grouping permutation
    perm_kernel<<<1, 1024>>>(idx);

    // 2) L1: per-game 512->1024, gather rows via perm, relu.
    //    16 y-tiles/game covers groups up to 2048 rows (idx~uniform: mean
    //    1024, sd~30 -> >17 sigma margin); empty tiles exit immediately.
    mma_gemm<128, 128, 16, 64, 32, 0>
        <<<dim3(H1D / 128, 16, GAMES), 256>>>(state, W1, b1, nullptr,
                                              DIN, H1D);

    // 3) L2: dense 1024->1024, relu
    mma_gemm<128, 128, 16, 64, 32, 1>
        <<<dim3(H2D / 128, BROWS / 128, 1), 256>>>(nullptr, W2, b2, nullptr,
                                                   H1D, H2D);

    // 4) L3 split-K: per-game 1024->128 partials over 8 K-chunks of 128.
    //    x = K-chunk (8), y = 32 row-tiles/game (2048-row capacity), z = game.
    //    ~1024 active CTAs (~7/SM).
    mma_gemm<64, 128, 16, 32, 32, 3>
        <<<dim3(SPLITK, 32, GAMES), 256>>>(nullptr, W3, nullptr, nullptr,
                                           H2D, ADIM);

    // 5) reduce + bias + tanh + scatter
    l3_reduce<<<BROWS * 32 / 256, 256>>>(b3, out);
}